// round 1
// baseline (speedup 1.0000x reference)
#include <cuda_runtime.h>
#include <math.h>

#define NN 50000
#define NE 400000
#define NG 64

// ---------------- static scratch (no allocations allowed) ----------------
__device__ float d_M[(size_t)NN * 384];
__device__ float d_aN[(size_t)NN * 4];
__device__ float d_h1[(size_t)NN * 96];
__device__ float d_h2[(size_t)NN * 96];
__device__ float d_h3[(size_t)NN * 64];
__device__ float d_S[(size_t)NN * 96];
__device__ int d_deg[NN];
__device__ int d_rowptr[NN + 1];
__device__ int d_cursor[NN];
__device__ int d_csrsrc[NE];
__device__ int d_gstart[NG + 1];
__device__ float d_pooled[NG * 64];

// ---------------- CSR build ----------------
__global__ void k_zero_deg() {
    int i = blockIdx.x * blockDim.x + threadIdx.x;
    if (i < NN) d_deg[i] = 0;
}

__global__ void k_degree(const int* __restrict__ dst) {
    int i = blockIdx.x * blockDim.x + threadIdx.x;
    if (i < NE) atomicAdd(&d_deg[dst[i]], 1);
}

// single-block exclusive scan of d_deg -> d_rowptr (N=50000 elements)
__global__ void k_scan() {
    __shared__ int sh[1024];
    __shared__ int carry;
    int tid = threadIdx.x;
    if (tid == 0) carry = 0;
    __syncthreads();
    for (int base = 0; base < NN; base += 1024) {
        int i = base + tid;
        int v = (i < NN) ? d_deg[i] : 0;
        sh[tid] = v;
        __syncthreads();
        #pragma unroll
        for (int off = 1; off < 1024; off <<= 1) {
            int t = (tid >= off) ? sh[tid - off] : 0;
            __syncthreads();
            sh[tid] += t;
            __syncthreads();
        }
        int incl = sh[tid];
        if (i < NN) d_rowptr[i] = carry + incl - v;
        __syncthreads();
        if (tid == 0) carry += sh[1023];
        __syncthreads();
    }
    if (threadIdx.x == 0) d_rowptr[NN] = carry;
}

__global__ void k_cursor() {
    int i = blockIdx.x * blockDim.x + threadIdx.x;
    if (i < NN) d_cursor[i] = d_rowptr[i];
}

__global__ void k_scatter(const int* __restrict__ src, const int* __restrict__ dst) {
    int i = blockIdx.x * blockDim.x + threadIdx.x;
    if (i < NE) {
        int p = atomicAdd(&d_cursor[dst[i]], 1);
        d_csrsrc[p] = src[i];
    }
}

// sort each row's source list ascending -> deterministic accumulation order
__global__ void k_sort() {
    int n = blockIdx.x * blockDim.x + threadIdx.x;
    if (n >= NN) return;
    int s = d_rowptr[n], e = d_rowptr[n + 1];
    for (int i = s + 1; i < e; i++) {
        int v = d_csrsrc[i];
        int j = i - 1;
        while (j >= s && d_csrsrc[j] > v) {
            d_csrsrc[j + 1] = d_csrsrc[j];
            j--;
        }
        d_csrsrc[j + 1] = v;
    }
}

// ---------------- SGEMM: C[M,Ncol] = A[M,K] @ B[K,Ncol] + bias ----------------
// BM=BN=128, BK=16, 256 threads, 8x8 micro-tile per thread.
__global__ __launch_bounds__(256, 2) void k_sgemm(
    const float* __restrict__ A, const float* __restrict__ B,
    const float* __restrict__ bias, float* __restrict__ C,
    int Mrows, int K, int Ncol)
{
    __shared__ float As[16][128];
    __shared__ float Bs[16][128];
    int tid = threadIdx.x;
    int r0 = blockIdx.x * 128;
    int n0 = blockIdx.y * 128;
    int tx = tid & 15, ty = tid >> 4;

    float acc[8][8];
    #pragma unroll
    for (int i = 0; i < 8; i++)
        #pragma unroll
        for (int j = 0; j < 8; j++) acc[i][j] = 0.f;

    for (int k0 = 0; k0 < K; k0 += 16) {
        // load A tile 128x16 (512 float4, 2 per thread), store transposed
        #pragma unroll
        for (int l = 0; l < 2; l++) {
            int li = tid * 2 + l;
            int row = li >> 2;
            int kq = (li & 3) * 4;
            float4 v = make_float4(0.f, 0.f, 0.f, 0.f);
            if (r0 + row < Mrows)
                v = *(const float4*)(A + (size_t)(r0 + row) * K + k0 + kq);
            As[kq + 0][row] = v.x;
            As[kq + 1][row] = v.y;
            As[kq + 2][row] = v.z;
            As[kq + 3][row] = v.w;
        }
        // load B tile 16x128
        #pragma unroll
        for (int l = 0; l < 2; l++) {
            int li = tid * 2 + l;
            int krow = li >> 5;
            int nq = (li & 31) * 4;
            float4 v = make_float4(0.f, 0.f, 0.f, 0.f);
            if (n0 + nq < Ncol)
                v = *(const float4*)(B + (size_t)(k0 + krow) * Ncol + n0 + nq);
            *(float4*)&Bs[krow][nq] = v;
        }
        __syncthreads();
        #pragma unroll
        for (int k = 0; k < 16; k++) {
            float a[8], b[8];
            *(float4*)&a[0] = *(float4*)&As[k][ty * 8];
            *(float4*)&a[4] = *(float4*)&As[k][ty * 8 + 4];
            *(float4*)&b[0] = *(float4*)&Bs[k][tx * 8];
            *(float4*)&b[4] = *(float4*)&Bs[k][tx * 8 + 4];
            #pragma unroll
            for (int i = 0; i < 8; i++)
                #pragma unroll
                for (int j = 0; j < 8; j++) acc[i][j] += a[i] * b[j];
        }
        __syncthreads();
    }
    // epilogue with bias
    #pragma unroll
    for (int i = 0; i < 8; i++) {
        int row = r0 + ty * 8 + i;
        if (row < Mrows) {
            #pragma unroll
            for (int j = 0; j < 8; j += 4) {
                int col = n0 + tx * 8 + j;
                if (col < Ncol) {
                    float4 bb = *(const float4*)(bias + col);
                    float4 o;
                    o.x = acc[i][j + 0] + bb.x;
                    o.y = acc[i][j + 1] + bb.y;
                    o.z = acc[i][j + 2] + bb.z;
                    o.w = acc[i][j + 3] + bb.w;
                    *(float4*)(C + (size_t)row * Ncol + col) = o;
                }
            }
        }
    }
}

// ---------------- per-node attention logits: aN[n,h] = leaky_relu(sum_c M[n,h,c]*att[h,c]) ----------------
template <int C>
__global__ __launch_bounds__(256) void k_alpha(const float* __restrict__ att) {
    const int HC = 4 * C;
    const int PL = HC / 32;
    int gw = (blockIdx.x * blockDim.x + threadIdx.x) >> 5;
    int lane = threadIdx.x & 31;
    if (gw >= NN) return;
    const float* row = d_M + (size_t)gw * HC + lane * PL;
    float s = 0.f;
    #pragma unroll
    for (int j = 0; j < PL; j++) s += row[j] * att[lane * PL + j];
    // reduce within 8-lane groups (one head spans 8 lanes)
    s += __shfl_xor_sync(0xffffffffu, s, 1);
    s += __shfl_xor_sync(0xffffffffu, s, 2);
    s += __shfl_xor_sync(0xffffffffu, s, 4);
    float a = (s > 0.f) ? s : 0.2f * s;  // leaky_relu slope 0.2
    if ((lane & 7) == 0) d_aN[(size_t)gw * 4 + (lane >> 3)] = a;
}

// ---------------- aggregation: one warp per destination node ----------------
// out[n,c] = resid[n,c] + (1/4) sum_h sum_{e in in(n)} softmax_w(e,h) * M[src(e), h, c]
template <int C>
__global__ __launch_bounds__(256) void k_agg(
    const float* __restrict__ resid, float* __restrict__ out)
{
    const int HC = 4 * C;
    const int PL = HC / 32;
    __shared__ float wsh[8][8][4];
    __shared__ int ssh[8][8];
    int gw = (blockIdx.x * blockDim.x + threadIdx.x) >> 5;
    int lane = threadIdx.x & 31;
    int wId = threadIdx.x >> 5;
    if (gw >= NN) return;
    int start = d_rowptr[gw], end = d_rowptr[gw + 1];

    // pass 1: per-head max of leaky logits over incoming edges
    float m0 = -INFINITY, m1 = -INFINITY, m2 = -INFINITY, m3 = -INFINITY;
    for (int i = start + lane; i < end; i += 32) {
        int s = d_csrsrc[i];
        float4 a = *(const float4*)(d_aN + (size_t)s * 4);
        m0 = fmaxf(m0, a.x);
        m1 = fmaxf(m1, a.y);
        m2 = fmaxf(m2, a.z);
        m3 = fmaxf(m3, a.w);
    }
    #pragma unroll
    for (int off = 16; off > 0; off >>= 1) {
        m0 = fmaxf(m0, __shfl_xor_sync(0xffffffffu, m0, off));
        m1 = fmaxf(m1, __shfl_xor_sync(0xffffffffu, m1, off));
        m2 = fmaxf(m2, __shfl_xor_sync(0xffffffffu, m2, off));
        m3 = fmaxf(m3, __shfl_xor_sync(0xffffffffu, m3, off));
    }
    int h = lane >> 3;   // head this lane's accumulator columns belong to
    int hh = lane & 3;   // head this lane computes exp-weights for
    float mhh = (hh == 0) ? m0 : (hh == 1) ? m1 : (hh == 2) ? m2 : m3;

    float acc[PL];
    #pragma unroll
    for (int j = 0; j < PL; j++) acc[j] = 0.f;
    float denL = 0.f;
    int ei = lane >> 2;  // edge slot (0..7) this lane computes weights for

    for (int base = start; base < end; base += 8) {
        int ne = end - base;
        if (ne > 8) ne = 8;
        float wl = 0.f;
        int sl = 0;
        if (ei < ne) {
            sl = d_csrsrc[base + ei];
            float a = d_aN[(size_t)sl * 4 + hh];
            wl = expf(a - mhh);
            wsh[wId][ei][hh] = wl;
            if (hh == 0) ssh[wId][ei] = sl;
        }
        denL += wl;
        __syncwarp();
        for (int e = 0; e < ne; e++) {
            int s = ssh[wId][e];
            float w = wsh[wId][e][h];
            const float4* mr = (const float4*)(d_M + (size_t)s * HC + lane * PL);
            #pragma unroll
            for (int q = 0; q < PL / 4; q++) {
                float4 v = mr[q];
                acc[q * 4 + 0] += w * v.x;
                acc[q * 4 + 1] += w * v.y;
                acc[q * 4 + 2] += w * v.z;
                acc[q * 4 + 3] += w * v.w;
            }
        }
        __syncwarp();
    }
    // reduce denominators: lanes with same hh form xor-{4,8,16} group
    denL += __shfl_xor_sync(0xffffffffu, denL, 4);
    denL += __shfl_xor_sync(0xffffffffu, denL, 8);
    denL += __shfl_xor_sync(0xffffffffu, denL, 16);
    float den = __shfl_sync(0xffffffffu, denL, h);  // lane h holds head-h denom
    float inv = 0.25f / (den + 1e-16f);             // fold head-mean (1/4)
    #pragma unroll
    for (int j = 0; j < PL; j++) {
        float v = acc[j] * inv;
        v += __shfl_xor_sync(0xffffffffu, v, 8);
        v += __shfl_xor_sync(0xffffffffu, v, 16);
        acc[j] = v;
    }
    if (lane < 8) {
        int col = lane * PL;
        #pragma unroll
        for (int q = 0; q < PL / 4; q++) {
            float4 r = *(const float4*)(resid + (size_t)gw * C + col + q * 4);
            float4 o;
            o.x = acc[q * 4 + 0] + r.x;
            o.y = acc[q * 4 + 1] + r.y;
            o.z = acc[q * 4 + 2] + r.z;
            o.w = acc[q * 4 + 3] + r.w;
            *(float4*)(out + (size_t)gw * C + col + q * 4) = o;
        }
    }
}

// ---------------- graph boundaries (batch is sorted) ----------------
__global__ void k_gstart(const int* __restrict__ batch) {
    int i = blockIdx.x * blockDim.x + threadIdx.x;
    if (i >= NN) return;
    int b = batch[i];
    int bp = (i == 0) ? -1 : batch[i - 1];
    for (int g = bp + 1; g <= b; g++) d_gstart[g] = i;
    if (i == NN - 1)
        for (int g = b + 1; g <= NG; g++) d_gstart[g] = NN;
}

// ---------------- global mean pool (deterministic per-graph reduce) ----------------
__global__ void k_pool() {
    int g = blockIdx.x;
    int start = d_gstart[g], end = d_gstart[g + 1];
    int c = threadIdx.x & 63;
    int stripe = threadIdx.x >> 6;  // 4 stripes of 64
    float acc = 0.f;
    for (int r = start + stripe; r < end; r += 4) acc += d_h3[(size_t)r * 64 + c];
    __shared__ float sh[256];
    sh[threadIdx.x] = acc;
    __syncthreads();
    if (stripe == 0) {
        float v = sh[c] + sh[c + 64] + sh[c + 128] + sh[c + 192];
        float cnt = (float)(end - start);
        d_pooled[g * 64 + c] = v / fmaxf(cnt, 1.0f);
    }
}

// ---------------- classifier + log_softmax ----------------
__global__ void k_fc(const float* __restrict__ Wfc, const float* __restrict__ bfc,
                     float* __restrict__ out) {
    int g = threadIdx.x;
    if (g >= NG) return;
    float logits[10];
    #pragma unroll
    for (int o = 0; o < 10; o++) {
        float s = bfc[o];
        for (int c = 0; c < 64; c++) s += d_pooled[g * 64 + c] * Wfc[c * 10 + o];
        logits[o] = s;
    }
    float mx = logits[0];
    #pragma unroll
    for (int o = 1; o < 10; o++) mx = fmaxf(mx, logits[o]);
    float se = 0.f;
    #pragma unroll
    for (int o = 0; o < 10; o++) se += expf(logits[o] - mx);
    float lse = mx + logf(se);
    #pragma unroll
    for (int o = 0; o < 10; o++) out[g * 10 + o] = logits[o] - lse;
}

// ---------------- launch ----------------
extern "C" void kernel_launch(void* const* d_in, const int* in_sizes, int n_in,
                              void* d_out, int out_size) {
    const float* x    = (const float*)d_in[0];
    const int* edge   = (const int*)d_in[1];
    const int* batch  = (const int*)d_in[2];
    const float* Wm1  = (const float*)d_in[3];
    const float* bm1  = (const float*)d_in[4];
    const float* att1 = (const float*)d_in[5];
    const float* Ws1  = (const float*)d_in[6];
    const float* bs1  = (const float*)d_in[7];
    const float* Wm2  = (const float*)d_in[8];
    const float* bm2  = (const float*)d_in[9];
    const float* att2 = (const float*)d_in[10];
    const float* Wm3  = (const float*)d_in[11];
    const float* bm3  = (const float*)d_in[12];
    const float* att3 = (const float*)d_in[13];
    const float* Ws3  = (const float*)d_in[14];
    const float* bs3  = (const float*)d_in[15];
    const float* Wfc  = (const float*)d_in[16];
    const float* bfc  = (const float*)d_in[17];
    float* out = (float*)d_out;

    const int* srcp = edge;
    const int* dstp = edge + NE;

    float *M, *S, *h1, *h2, *h3;
    cudaGetSymbolAddress((void**)&M, d_M);
    cudaGetSymbolAddress((void**)&S, d_S);
    cudaGetSymbolAddress((void**)&h1, d_h1);
    cudaGetSymbolAddress((void**)&h2, d_h2);
    cudaGetSymbolAddress((void**)&h3, d_h3);

    const int TB = 256;
    const int nodeBlocks = (NN + TB - 1) / TB;          // 196
    const int edgeBlocks = (NE + TB - 1) / TB;          // 1563
    const int warpNodeBlocks = (NN * 32 + TB - 1) / TB; // 6250
    const int rowBlocks = (NN + 127) / 128;             // 391

    // CSR build (shared by all 3 layers)
    k_zero_deg<<<nodeBlocks, TB>>>();
    k_degree<<<edgeBlocks, TB>>>(dstp);
    k_scan<<<1, 1024>>>();
    k_cursor<<<nodeBlocks, TB>>>();
    k_scatter<<<edgeBlocks, TB>>>(srcp, dstp);
    k_sort<<<nodeBlocks, TB>>>();

    // ---- layer 1: F_IN=64 -> H1=96 ----
    k_sgemm<<<dim3(rowBlocks, 3), TB>>>(x, Wm1, bm1, M, NN, 64, 384);
    k_sgemm<<<dim3(rowBlocks, 1), TB>>>(x, Ws1, bs1, S, NN, 64, 96);
    k_alpha<96><<<warpNodeBlocks, TB>>>(att1);
    k_agg<96><<<warpNodeBlocks, TB>>>(S, h1);

    // ---- layer 2: 96 -> 96 (identity self loop) ----
    k_sgemm<<<dim3(rowBlocks, 3), TB>>>(h1, Wm2, bm2, M, NN, 96, 384);
    k_alpha<96><<<warpNodeBlocks, TB>>>(att2);
    k_agg<96><<<warpNodeBlocks, TB>>>(h1, h2);

    // ---- layer 3: 96 -> 64 ----
    k_sgemm<<<dim3(rowBlocks, 2), TB>>>(h2, Wm3, bm3, M, NN, 96, 256);
    k_sgemm<<<dim3(rowBlocks, 1), TB>>>(h2, Ws3, bs3, S, NN, 96, 64);
    k_alpha<64><<<warpNodeBlocks, TB>>>(att3);
    k_agg<64><<<warpNodeBlocks, TB>>>(S, h3);

    // ---- pool + classifier ----
    k_gstart<<<nodeBlocks, TB>>>(batch);
    k_pool<<<NG, 256>>>();
    k_fc<<<1, 64>>>(Wfc, bfc, out);
}

// round 3
// speedup vs baseline: 1.2055x; 1.2055x over previous
#include <cuda_runtime.h>
#include <cuda_bf16.h>
#include <math.h>
#include <stdint.h>

#define NN 50000
#define NE 400000
#define NG 64

// ---------------- static scratch (no allocations allowed) ----------------
__device__ float d_M[(size_t)NN * 384];
__device__ float d_aN[(size_t)NN * 4];
__device__ float d_h1[(size_t)NN * 96];
__device__ float d_h2[(size_t)NN * 96];
__device__ float d_h3[(size_t)NN * 64];
__device__ float d_S[(size_t)NN * 96];
__device__ int d_deg[NN];
__device__ int d_rowptr[NN + 1];
__device__ int d_cursor[NN];
__device__ int d_csrsrc[NE];
__device__ int d_gstart[NG + 1];
__device__ float d_pooled[NG * 64];
// W'^T = [Nout x 3K] bf16: cols [Whi | Wlo | Whi]
__device__ __align__(16) __nv_bfloat16 d_Wbf[(size_t)384 * 288];

// ---------------- CSR build ----------------
__global__ void k_zero_deg() {
    int i = blockIdx.x * blockDim.x + threadIdx.x;
    if (i < NN) d_deg[i] = 0;
}

__global__ void k_degree(const int* __restrict__ dst) {
    int i = blockIdx.x * blockDim.x + threadIdx.x;
    if (i < NE) atomicAdd(&d_deg[dst[i]], 1);
}

__global__ void k_scan() {
    __shared__ int sh[1024];
    __shared__ int carry;
    int tid = threadIdx.x;
    if (tid == 0) carry = 0;
    __syncthreads();
    for (int base = 0; base < NN; base += 1024) {
        int i = base + tid;
        int v = (i < NN) ? d_deg[i] : 0;
        sh[tid] = v;
        __syncthreads();
        #pragma unroll
        for (int off = 1; off < 1024; off <<= 1) {
            int t = (tid >= off) ? sh[tid - off] : 0;
            __syncthreads();
            sh[tid] += t;
            __syncthreads();
        }
        int incl = sh[tid];
        if (i < NN) d_rowptr[i] = carry + incl - v;
        __syncthreads();
        if (tid == 0) carry += sh[1023];
        __syncthreads();
    }
    if (threadIdx.x == 0) d_rowptr[NN] = carry;
}

__global__ void k_cursor() {
    int i = blockIdx.x * blockDim.x + threadIdx.x;
    if (i < NN) d_cursor[i] = d_rowptr[i];
}

__global__ void k_scatter(const int* __restrict__ src, const int* __restrict__ dst) {
    int i = blockIdx.x * blockDim.x + threadIdx.x;
    if (i < NE) {
        int p = atomicAdd(&d_cursor[dst[i]], 1);
        d_csrsrc[p] = src[i];
    }
}

__global__ void k_sort() {
    int n = blockIdx.x * blockDim.x + threadIdx.x;
    if (n >= NN) return;
    int s = d_rowptr[n], e = d_rowptr[n + 1];
    for (int i = s + 1; i < e; i++) {
        int v = d_csrsrc[i];
        int j = i - 1;
        while (j >= s && d_csrsrc[j] > v) {
            d_csrsrc[j + 1] = d_csrsrc[j];
            j--;
        }
        d_csrsrc[j + 1] = v;
    }
}

// ---------------- W split conversion: W [K x Nout] fp32 -> [Nout x 3K] bf16 ----------------
__global__ void k_convW(const float* __restrict__ W, int K, int Nout) {
    int idx = blockIdx.x * blockDim.x + threadIdx.x;
    if (idx >= K * Nout) return;
    int k = idx / Nout, n = idx - k * Nout;
    float w = W[idx];
    __nv_bfloat16 hi = __float2bfloat16(w);
    __nv_bfloat16 lo = __float2bfloat16(w - __bfloat162float(hi));
    size_t base = (size_t)n * (3 * K);
    d_Wbf[base + k] = hi;          // pairs with A-hi (region 0)
    d_Wbf[base + K + k] = lo;      // pairs with A-hi (region 1)
    d_Wbf[base + 2 * K + k] = hi;  // pairs with A-lo (region 2)
}

// ---------------- bf16 MMA GEMM (legacy mma.sync, baseline PTX) ----------------
// C[r,n] = sum over K'=3K of Abf'[r,k']*Wbf[n,k'] + bias[n]
// A fp32 [Mrows x K] split on the fly into regions [hi|hi|lo].
// BM=128, BN=128, BK=32; 8 warps (4x2), warp tile 32x64 via m16n8k16.

__device__ __forceinline__ uint32_t swz_off(int row, int c16) {
    // 64B rows of bf16 (32 elems = 4 x 16B chunks); chunk xor (row>>1)&3
    return (uint32_t)((row << 6) + (((c16 ^ ((row >> 1) & 3)) & 3) << 4));
}

__global__ __launch_bounds__(256) void k_hgemm(
    const float* __restrict__ A, int K,
    const float* __restrict__ bias, float* __restrict__ C,
    int Mrows, int Nout)
{
    __shared__ __align__(16) char As[128 * 64];
    __shared__ __align__(16) char Bs[128 * 64];
    int tid = threadIdx.x;
    int wid = tid >> 5, lane = tid & 31;
    int r0 = blockIdx.x * 128;
    int n0 = blockIdx.y * 128;
    int wm = (wid & 3) * 32;      // warp m-offset within tile
    int wn = (wid >> 2) * 64;     // warp n-offset within tile

    uint32_t AsAddr = (uint32_t)__cvta_generic_to_shared(As);
    uint32_t BsAddr = (uint32_t)__cvta_generic_to_shared(Bs);

    float acc[2][8][4];
    #pragma unroll
    for (int i = 0; i < 2; i++)
        #pragma unroll
        for (int j = 0; j < 8; j++)
            #pragma unroll
            for (int q = 0; q < 4; q++) acc[i][j][q] = 0.f;

    const __nv_bfloat16* Bw = d_Wbf;
    int Kreal = 3 * K;

    for (int kb = 0; kb < Kreal; kb += 32) {
        int region = kb / K;              // 0,1 -> hi ; 2 -> lo (K multiple of 32)
        int kc = kb - region * K;
        bool isLo = (region == 2);

        // ---- load + convert A tile: 128 rows x 32 fp32 -> bf16 ----
        #pragma unroll
        for (int it = 0; it < 2; it++) {
            int linear = tid + it * 256;      // 512 chunks of 8 elems
            int row = linear >> 2;
            int c8 = (linear & 3) << 3;
            int gr = r0 + row;
            float v[8];
            if (gr < Mrows) {
                float4 u0 = *(const float4*)(A + (size_t)gr * K + kc + c8);
                float4 u1 = *(const float4*)(A + (size_t)gr * K + kc + c8 + 4);
                v[0] = u0.x; v[1] = u0.y; v[2] = u0.z; v[3] = u0.w;
                v[4] = u1.x; v[5] = u1.y; v[6] = u1.z; v[7] = u1.w;
            } else {
                #pragma unroll
                for (int j = 0; j < 8; j++) v[j] = 0.f;
            }
            uint32_t pk[4];
            #pragma unroll
            for (int j = 0; j < 4; j++) {
                __nv_bfloat16 h0 = __float2bfloat16(v[2 * j]);
                __nv_bfloat16 h1 = __float2bfloat16(v[2 * j + 1]);
                __nv_bfloat16 e0 = isLo ? __float2bfloat16(v[2 * j] - __bfloat162float(h0)) : h0;
                __nv_bfloat16 e1 = isLo ? __float2bfloat16(v[2 * j + 1] - __bfloat162float(h1)) : h1;
                pk[j] = (uint32_t)__bfloat16_as_ushort(e0)
                      | ((uint32_t)__bfloat16_as_ushort(e1) << 16);
            }
            *(uint4*)(As + swz_off(row, c8 >> 3)) = make_uint4(pk[0], pk[1], pk[2], pk[3]);
        }
        // ---- load B tile: 128 n-rows x 32 bf16 from d_Wbf ----
        #pragma unroll
        for (int it = 0; it < 2; it++) {
            int linear = tid + it * 256;
            int row = linear >> 2;
            int c8 = (linear & 3) << 3;
            int gn = n0 + row;
            uint4 v = make_uint4(0u, 0u, 0u, 0u);
            if (gn < Nout)
                v = *(const uint4*)(Bw + (size_t)gn * Kreal + kb + c8);
            *(uint4*)(Bs + swz_off(row, c8 >> 3)) = v;
        }
        __syncthreads();

        // ---- compute: two k16 steps ----
        #pragma unroll
        for (int ks = 0; ks < 32; ks += 16) {
            uint32_t aF[2][4], bF[8][2];
            #pragma unroll
            for (int mt = 0; mt < 2; mt++) {
                int q = lane >> 3;                       // quadrant 0..3
                int row = wm + mt * 16 + ((q & 1) << 3) + (lane & 7);
                int c16 = (ks >> 3) + (q >> 1);
                uint32_t addr = AsAddr + swz_off(row, c16);
                asm volatile("ldmatrix.sync.aligned.m8n8.x4.shared.b16 {%0,%1,%2,%3}, [%4];"
                    : "=r"(aF[mt][0]), "=r"(aF[mt][1]), "=r"(aF[mt][2]), "=r"(aF[mt][3])
                    : "r"(addr));
            }
            #pragma unroll
            for (int np = 0; np < 4; np++) {             // pairs of n-tiles
                int q = lane >> 3;
                int row = wn + np * 16 + ((q >> 1) << 3) + (lane & 7);
                int c16 = (ks >> 3) + (q & 1);
                uint32_t addr = BsAddr + swz_off(row, c16);
                asm volatile("ldmatrix.sync.aligned.m8n8.x4.shared.b16 {%0,%1,%2,%3}, [%4];"
                    : "=r"(bF[2 * np][0]), "=r"(bF[2 * np][1]),
                      "=r"(bF[2 * np + 1][0]), "=r"(bF[2 * np + 1][1])
                    : "r"(addr));
            }
            #pragma unroll
            for (int mt = 0; mt < 2; mt++)
                #pragma unroll
                for (int nt = 0; nt < 8; nt++) {
                    asm volatile(
                        "mma.sync.aligned.m16n8k16.row.col.f32.bf16.bf16.f32 "
                        "{%0,%1,%2,%3}, {%4,%5,%6,%7}, {%8,%9}, {%0,%1,%2,%3};"
                        : "+f"(acc[mt][nt][0]), "+f"(acc[mt][nt][1]),
                          "+f"(acc[mt][nt][2]), "+f"(acc[mt][nt][3])
                        : "r"(aF[mt][0]), "r"(aF[mt][1]), "r"(aF[mt][2]), "r"(aF[mt][3]),
                          "r"(bF[nt][0]), "r"(bF[nt][1]));
                }
        }
        __syncthreads();
    }

    // ---- epilogue: acc layout d0,d1:(m, n..n+1)  d2,d3:(m+8, n..n+1) ----
    #pragma unroll
    for (int mt = 0; mt < 2; mt++) {
        int m = r0 + wm + mt * 16 + (lane >> 2);
        #pragma unroll
        for (int nt = 0; nt < 8; nt++) {
            int n = n0 + wn + nt * 8 + (lane & 3) * 2;
            if (n < Nout) {
                float2 bb = *(const float2*)(bias + n);
                if (m < Mrows) {
                    float2 o0;
                    o0.x = acc[mt][nt][0] + bb.x;
                    o0.y = acc[mt][nt][1] + bb.y;
                    *(float2*)(C + (size_t)m * Nout + n) = o0;
                }
                if (m + 8 < Mrows) {
                    float2 o1;
                    o1.x = acc[mt][nt][2] + bb.x;
                    o1.y = acc[mt][nt][3] + bb.y;
                    *(float2*)(C + (size_t)(m + 8) * Nout + n) = o1;
                }
            }
        }
    }
}

// ---------------- per-node attention logits ----------------
template <int C>
__global__ __launch_bounds__(256) void k_alpha(const float* __restrict__ att) {
    const int HC = 4 * C;
    const int PL = HC / 32;
    int gw = (blockIdx.x * blockDim.x + threadIdx.x) >> 5;
    int lane = threadIdx.x & 31;
    if (gw >= NN) return;
    const float* row = d_M + (size_t)gw * HC + lane * PL;
    float s = 0.f;
    #pragma unroll
    for (int j = 0; j < PL; j++) s += row[j] * att[lane * PL + j];
    s += __shfl_xor_sync(0xffffffffu, s, 1);
    s += __shfl_xor_sync(0xffffffffu, s, 2);
    s += __shfl_xor_sync(0xffffffffu, s, 4);
    float a = (s > 0.f) ? s : 0.2f * s;
    if ((lane & 7) == 0) d_aN[(size_t)gw * 4 + (lane >> 3)] = a;
}

// ---------------- aggregation: one warp per destination node ----------------
template <int C>
__global__ __launch_bounds__(256) void k_agg(
    const float* __restrict__ resid, float* __restrict__ out)
{
    const int HC = 4 * C;
    const int PL = HC / 32;
    __shared__ float wsh[8][8][4];
    __shared__ int ssh[8][8];
    int gw = (blockIdx.x * blockDim.x + threadIdx.x) >> 5;
    int lane = threadIdx.x & 31;
    int wId = threadIdx.x >> 5;
    if (gw >= NN) return;
    int start = d_rowptr[gw], end = d_rowptr[gw + 1];

    float m0 = -INFINITY, m1 = -INFINITY, m2 = -INFINITY, m3 = -INFINITY;
    for (int i = start + lane; i < end; i += 32) {
        int s = d_csrsrc[i];
        float4 a = *(const float4*)(d_aN + (size_t)s * 4);
        m0 = fmaxf(m0, a.x);
        m1 = fmaxf(m1, a.y);
        m2 = fmaxf(m2, a.z);
        m3 = fmaxf(m3, a.w);
    }
    #pragma unroll
    for (int off = 16; off > 0; off >>= 1) {
        m0 = fmaxf(m0, __shfl_xor_sync(0xffffffffu, m0, off));
        m1 = fmaxf(m1, __shfl_xor_sync(0xffffffffu, m1, off));
        m2 = fmaxf(m2, __shfl_xor_sync(0xffffffffu, m2, off));
        m3 = fmaxf(m3, __shfl_xor_sync(0xffffffffu, m3, off));
    }
    int h = lane >> 3;
    int hh = lane & 3;
    float mhh = (hh == 0) ? m0 : (hh == 1) ? m1 : (hh == 2) ? m2 : m3;

    float acc[PL];
    #pragma unroll
    for (int j = 0; j < PL; j++) acc[j] = 0.f;
    float denL = 0.f;
    int ei = lane >> 2;

    for (int base = start; base < end; base += 8) {
        int ne = end - base;
        if (ne > 8) ne = 8;
        float wl = 0.f;
        int sl = 0;
        if (ei < ne) {
            sl = d_csrsrc[base + ei];
            float a = d_aN[(size_t)sl * 4 + hh];
            wl = expf(a - mhh);
            wsh[wId][ei][hh] = wl;
            if (hh == 0) ssh[wId][ei] = sl;
        }
        denL += wl;
        __syncwarp();
        for (int e = 0; e < ne; e++) {
            int s = ssh[wId][e];
            float w = wsh[wId][e][h];
            const float4* mr = (const float4*)(d_M + (size_t)s * HC + lane * PL);
            #pragma unroll
            for (int q = 0; q < PL / 4; q++) {
                float4 v = mr[q];
                acc[q * 4 + 0] += w * v.x;
                acc[q * 4 + 1] += w * v.y;
                acc[q * 4 + 2] += w * v.z;
                acc[q * 4 + 3] += w * v.w;
            }
        }
        __syncwarp();
    }
    denL += __shfl_xor_sync(0xffffffffu, denL, 4);
    denL += __shfl_xor_sync(0xffffffffu, denL, 8);
    denL += __shfl_xor_sync(0xffffffffu, denL, 16);
    float den = __shfl_sync(0xffffffffu, denL, h);
    float inv = 0.25f / (den + 1e-16f);
    #pragma unroll
    for (int j = 0; j < PL; j++) {
        float v = acc[j] * inv;
        v += __shfl_xor_sync(0xffffffffu, v, 8);
        v += __shfl_xor_sync(0xffffffffu, v, 16);
        acc[j] = v;
    }
    if (lane < 8) {
        int col = lane * PL;
        #pragma unroll
        for (int q = 0; q < PL / 4; q++) {
            float4 r = *(const float4*)(resid + (size_t)gw * C + col + q * 4);
            float4 o;
            o.x = acc[q * 4 + 0] + r.x;
            o.y = acc[q * 4 + 1] + r.y;
            o.z = acc[q * 4 + 2] + r.z;
            o.w = acc[q * 4 + 3] + r.w;
            *(float4*)(out + (size_t)gw * C + col + q * 4) = o;
        }
    }
}

// ---------------- graph boundaries ----------------
__global__ void k_gstart(const int* __restrict__ batch) {
    int i = blockIdx.x * blockDim.x + threadIdx.x;
    if (i >= NN) return;
    int b = batch[i];
    int bp = (i == 0) ? -1 : batch[i - 1];
    for (int g = bp + 1; g <= b; g++) d_gstart[g] = i;
    if (i == NN - 1)
        for (int g = b + 1; g <= NG; g++) d_gstart[g] = NN;
}

// ---------------- global mean pool ----------------
__global__ void k_pool() {
    int g = blockIdx.x;
    int start = d_gstart[g], end = d_gstart[g + 1];
    int c = threadIdx.x & 63;
    int stripe = threadIdx.x >> 6;
    float acc = 0.f;
    for (int r = start + stripe; r < end; r += 4) acc += d_h3[(size_t)r * 64 + c];
    __shared__ float sh[256];
    sh[threadIdx.x] = acc;
    __syncthreads();
    if (stripe == 0) {
        float v = sh[c] + sh[c + 64] + sh[c + 128] + sh[c + 192];
        float cnt = (float)(end - start);
        d_pooled[g * 64 + c] = v / fmaxf(cnt, 1.0f);
    }
}

// ---------------- classifier + log_softmax ----------------
__global__ void k_fc(const float* __restrict__ Wfc, const float* __restrict__ bfc,
                     float* __restrict__ out) {
    int g = threadIdx.x;
    if (g >= NG) return;
    float logits[10];
    #pragma unroll
    for (int o = 0; o < 10; o++) {
        float s = bfc[o];
        for (int c = 0; c < 64; c++) s += d_pooled[g * 64 + c] * Wfc[c * 10 + o];
        logits[o] = s;
    }
    float mx = logits[0];
    #pragma unroll
    for (int o = 1; o < 10; o++) mx = fmaxf(mx, logits[o]);
    float se = 0.f;
    #pragma unroll
    for (int o = 0; o < 10; o++) se += expf(logits[o] - mx);
    float lse = mx + logf(se);
    #pragma unroll
    for (int o = 0; o < 10; o++) out[g * 10 + o] = logits[o] - lse;
}

// ---------------- launch ----------------
extern "C" void kernel_launch(void* const* d_in, const int* in_sizes, int n_in,
                              void* d_out, int out_size) {
    const float* x    = (const float*)d_in[0];
    const int* edge   = (const int*)d_in[1];
    const int* batch  = (const int*)d_in[2];
    const float* Wm1  = (const float*)d_in[3];
    const float* bm1  = (const float*)d_in[4];
    const float* att1 = (const float*)d_in[5];
    const float* Ws1  = (const float*)d_in[6];
    const float* bs1  = (const float*)d_in[7];
    const float* Wm2  = (const float*)d_in[8];
    const float* bm2  = (const float*)d_in[9];
    const float* att2 = (const float*)d_in[10];
    const float* Wm3  = (const float*)d_in[11];
    const float* bm3  = (const float*)d_in[12];
    const float* att3 = (const float*)d_in[13];
    const float* Ws3  = (const float*)d_in[14];
    const float* bs3  = (const float*)d_in[15];
    const float* Wfc  = (const float*)d_in[16];
    const float* bfc  = (const float*)d_in[17];
    float* out = (float*)d_out;

    const int* srcp = edge;
    const int* dstp = edge + NE;

    float *M, *S, *h1, *h2, *h3;
    cudaGetSymbolAddress((void**)&M, d_M);
    cudaGetSymbolAddress((void**)&S, d_S);
    cudaGetSymbolAddress((void**)&h1, d_h1);
    cudaGetSymbolAddress((void**)&h2, d_h2);
    cudaGetSymbolAddress((void**)&h3, d_h3);

    const int TB = 256;
    const int nodeBlocks = (NN + TB - 1) / TB;
    const int edgeBlocks = (NE + TB - 1) / TB;
    const int warpNodeBlocks = (NN * 32 + TB - 1) / TB;
    const int rowBlocks = (NN + 127) / 128;   // 391

    // CSR build
    k_zero_deg<<<nodeBlocks, TB>>>();
    k_degree<<<edgeBlocks, TB>>>(dstp);
    k_scan<<<1, 1024>>>();
    k_cursor<<<nodeBlocks, TB>>>();
    k_scatter<<<edgeBlocks, TB>>>(srcp, dstp);
    k_sort<<<nodeBlocks, TB>>>();

    // ---- layer 1: K=64 ----
    k_convW<<<(64 * 384 + TB - 1) / TB, TB>>>(Wm1, 64, 384);
    k_hgemm<<<dim3(rowBlocks, 3), TB>>>(x, 64, bm1, M, NN, 384);
    k_convW<<<(64 * 96 + TB - 1) / TB, TB>>>(Ws1, 64, 96);
    k_hgemm<<<dim3(rowBlocks, 1), TB>>>(x, 64, bs1, S, NN, 96);
    k_alpha<96><<<warpNodeBlocks, TB>>>(att1);
    k_agg<96><<<warpNodeBlocks, TB>>>(S, h1);

    // ---- layer 2: K=96 ----
    k_convW<<<(96 * 384 + TB - 1) / TB, TB>>>(Wm2, 96, 384);
    k_hgemm<<<dim3(rowBlocks, 3), TB>>>(h1, 96, bm2, M, NN, 384);
    k_alpha<96><<<warpNodeBlocks, TB>>>(att2);
    k_agg<96><<<warpNodeBlocks, TB>>>(h1, h2);

    // ---- layer 3: K=96 ----
    k_convW<<<(96 * 256 + TB - 1) / TB, TB>>>(Wm3, 96, 256);
    k_hgemm<<<dim3(rowBlocks, 2), TB>>>(h2, 96, bm3, M, NN, 256);
    k_convW<<<(96 * 64 + TB - 1) / TB, TB>>>(Ws3, 96, 64);
    k_hgemm<<<dim3(rowBlocks, 1), TB>>>(h2, 96, bs3, S, NN, 64);
    k_alpha<64><<<warpNodeBlocks, TB>>>(att3);
    k_agg<64><<<warpNodeBlocks, TB>>>(S, h3);

    // ---- pool + classifier ----
    k_gstart<<<nodeBlocks, TB>>>(batch);
    k_pool<<<NG, 256>>>();
    k_fc<<<1, 64>>>(Wfc, bfc, out);
}

// round 4
// speedup vs baseline: 1.7328x; 1.4375x over previous
#include <cuda_runtime.h>
#include <cuda_fp16.h>
#include <math.h>
#include <stdint.h>

#define NN 50000
#define NE 400000
#define NG 64

// ---------------- static scratch (no allocations allowed) ----------------
__device__ __align__(16) __half d_Mh[(size_t)NN * 384];  // messages, fp16
__device__ float d_aN[(size_t)NN * 4];
__device__ float d_h1[(size_t)NN * 96];
__device__ float d_h2[(size_t)NN * 96];
__device__ float d_h3[(size_t)NN * 64];
__device__ float d_S[(size_t)NN * 96];
__device__ int d_deg[NN];
__device__ int d_rowptr[NN + 1];
__device__ int d_cursor[NN];
__device__ int d_csrsrc[NE];
__device__ int d_gstart[NG + 1];
__device__ float d_pooled[NG * 64];
// W'^T = [Nout x 2K] fp16: cols [Whi | Wlo]
__device__ __align__(16) __half d_Wh[(size_t)384 * 192];

// ---------------- CSR build ----------------
__global__ void k_zero_deg() {
    int i = blockIdx.x * blockDim.x + threadIdx.x;
    if (i < NN) d_deg[i] = 0;
}

__global__ void k_degree(const int* __restrict__ dst) {
    int i = blockIdx.x * blockDim.x + threadIdx.x;
    if (i < NE) atomicAdd(&d_deg[dst[i]], 1);
}

// warp-shuffle exclusive scan of d_deg -> d_rowptr
__global__ void k_scan() {
    __shared__ int wsum[32];
    __shared__ int carrySh;
    int tid = threadIdx.x;
    int lane = tid & 31, w = tid >> 5;
    if (tid == 0) carrySh = 0;
    __syncthreads();
    for (int base = 0; base < NN; base += 1024) {
        int i = base + tid;
        int v = (i < NN) ? d_deg[i] : 0;
        int incl = v;
        #pragma unroll
        for (int off = 1; off < 32; off <<= 1) {
            int t = __shfl_up_sync(0xffffffffu, incl, off);
            if (lane >= off) incl += t;
        }
        if (lane == 31) wsum[w] = incl;
        __syncthreads();
        if (w == 0) {
            int s = wsum[lane];
            #pragma unroll
            for (int off = 1; off < 32; off <<= 1) {
                int t = __shfl_up_sync(0xffffffffu, s, off);
                if (lane >= off) s += t;
            }
            wsum[lane] = s;
        }
        __syncthreads();
        int woff = (w > 0) ? wsum[w - 1] : 0;
        int carry = carrySh;
        int total = wsum[31];
        __syncthreads();
        if (i < NN) d_rowptr[i] = carry + woff + incl - v;
        if (tid == 0) carrySh = carry + total;
        __syncthreads();
    }
    if (tid == 0) d_rowptr[NN] = carrySh;
}

__global__ void k_cursor() {
    int i = blockIdx.x * blockDim.x + threadIdx.x;
    if (i < NN) d_cursor[i] = d_rowptr[i];
}

__global__ void k_scatter(const int* __restrict__ src, const int* __restrict__ dst) {
    int i = blockIdx.x * blockDim.x + threadIdx.x;
    if (i < NE) {
        int p = atomicAdd(&d_cursor[dst[i]], 1);
        d_csrsrc[p] = src[i];
    }
}

__global__ void k_sort() {
    int n = blockIdx.x * blockDim.x + threadIdx.x;
    if (n >= NN) return;
    int s = d_rowptr[n], e = d_rowptr[n + 1];
    for (int i = s + 1; i < e; i++) {
        int v = d_csrsrc[i];
        int j = i - 1;
        while (j >= s && d_csrsrc[j] > v) {
            d_csrsrc[j + 1] = d_csrsrc[j];
            j--;
        }
        d_csrsrc[j + 1] = v;
    }
}

// ---------------- W split conversion: W [K x Nout] fp32 -> [Nout x 2K] fp16 ----------------
__global__ void k_convW(const float* __restrict__ W, int K, int Nout) {
    int idx = blockIdx.x * blockDim.x + threadIdx.x;
    if (idx >= K * Nout) return;
    int k = idx / Nout, n = idx - k * Nout;
    float w = W[idx];
    __half hi = __float2half(w);
    __half lo = __float2half(w - __half2float(hi));
    size_t base = (size_t)n * (2 * K);
    d_Wh[base + k] = hi;       // pairs with A (region 0)
    d_Wh[base + K + k] = lo;   // pairs with A (region 1)
}

// ---------------- fp16 MMA GEMM (mma.sync m16n8k16, baseline PTX) ----------------
// C[r,n] = sum over K'=2K of A16[r,k']*Wh[n,k'] + bias[n]; A regions [A|A], W [hi|lo].
// BM=128, BN=128, BK=32; 8 warps (4x2), warp tile 32x64.

__device__ __forceinline__ uint32_t swz_off(int row, int c16) {
    // 64B rows (32 halves = 4 x 16B chunks); chunk xor (row>>1)&3
    return (uint32_t)((row << 6) + (((c16 ^ ((row >> 1) & 3)) & 3) << 4));
}

template <typename OutT>
__global__ __launch_bounds__(256) void k_hgemm(
    const float* __restrict__ A, int K,
    const float* __restrict__ bias, OutT* __restrict__ C,
    int Mrows, int Nout)
{
    __shared__ __align__(16) char As[128 * 64];
    __shared__ __align__(16) char Bs[128 * 64];
    int tid = threadIdx.x;
    int wid = tid >> 5, lane = tid & 31;
    int r0 = blockIdx.x * 128;
    int n0 = blockIdx.y * 128;
    int wm = (wid & 3) * 32;
    int wn = (wid >> 2) * 64;

    uint32_t AsAddr = (uint32_t)__cvta_generic_to_shared(As);
    uint32_t BsAddr = (uint32_t)__cvta_generic_to_shared(Bs);

    float acc[2][8][4];
    #pragma unroll
    for (int i = 0; i < 2; i++)
        #pragma unroll
        for (int j = 0; j < 8; j++)
            #pragma unroll
            for (int q = 0; q < 4; q++) acc[i][j][q] = 0.f;

    int Kreal = 2 * K;

    for (int kb = 0; kb < Kreal; kb += 32) {
        int kc = (kb >= K) ? kb - K : kb;   // both regions read the same A data

        // ---- load + convert A tile: 128 rows x 32 fp32 -> fp16 ----
        #pragma unroll
        for (int it = 0; it < 2; it++) {
            int linear = tid + it * 256;
            int row = linear >> 2;
            int c8 = (linear & 3) << 3;
            int gr = r0 + row;
            float v[8];
            if (gr < Mrows) {
                float4 u0 = *(const float4*)(A + (size_t)gr * K + kc + c8);
                float4 u1 = *(const float4*)(A + (size_t)gr * K + kc + c8 + 4);
                v[0] = u0.x; v[1] = u0.y; v[2] = u0.z; v[3] = u0.w;
                v[4] = u1.x; v[5] = u1.y; v[6] = u1.z; v[7] = u1.w;
            } else {
                #pragma unroll
                for (int j = 0; j < 8; j++) v[j] = 0.f;
            }
            uint32_t pk[4];
            #pragma unroll
            for (int j = 0; j < 4; j++) {
                __half2 h = __floats2half2_rn(v[2 * j], v[2 * j + 1]);
                pk[j] = *(uint32_t*)&h;
            }
            *(uint4*)(As + swz_off(row, c8 >> 3)) = make_uint4(pk[0], pk[1], pk[2], pk[3]);
        }
        // ---- load B tile: 128 n-rows x 32 fp16 from d_Wh ----
        #pragma unroll
        for (int it = 0; it < 2; it++) {
            int linear = tid + it * 256;
            int row = linear >> 2;
            int c8 = (linear & 3) << 3;
            int gn = n0 + row;
            uint4 v = make_uint4(0u, 0u, 0u, 0u);
            if (gn < Nout)
                v = *(const uint4*)(d_Wh + (size_t)gn * Kreal + kb + c8);
            *(uint4*)(Bs + swz_off(row, c8 >> 3)) = v;
        }
        __syncthreads();

        // ---- compute: two k16 steps ----
        #pragma unroll
        for (int ks = 0; ks < 32; ks += 16) {
            uint32_t aF[2][4], bF[8][2];
            #pragma unroll
            for (int mt = 0; mt < 2; mt++) {
                int q = lane >> 3;
                int row = wm + mt * 16 + ((q & 1) << 3) + (lane & 7);
                int c16 = (ks >> 3) + (q >> 1);
                uint32_t addr = AsAddr + swz_off(row, c16);
                asm volatile("ldmatrix.sync.aligned.m8n8.x4.shared.b16 {%0,%1,%2,%3}, [%4];"
                    : "=r"(aF[mt][0]), "=r"(aF[mt][1]), "=r"(aF[mt][2]), "=r"(aF[mt][3])
                    : "r"(addr));
            }
            #pragma unroll
            for (int np = 0; np < 4; np++) {
                int q = lane >> 3;
                int row = wn + np * 16 + ((q >> 1) << 3) + (lane & 7);
                int c16 = (ks >> 3) + (q & 1);
                uint32_t addr = BsAddr + swz_off(row, c16);
                asm volatile("ldmatrix.sync.aligned.m8n8.x4.shared.b16 {%0,%1,%2,%3}, [%4];"
                    : "=r"(bF[2 * np][0]), "=r"(bF[2 * np][1]),
                      "=r"(bF[2 * np + 1][0]), "=r"(bF[2 * np + 1][1])
                    : "r"(addr));
            }
            #pragma unroll
            for (int mt = 0; mt < 2; mt++)
                #pragma unroll
                for (int nt = 0; nt < 8; nt++) {
                    asm volatile(
                        "mma.sync.aligned.m16n8k16.row.col.f32.f16.f16.f32 "
                        "{%0,%1,%2,%3}, {%4,%5,%6,%7}, {%8,%9}, {%0,%1,%2,%3};"
                        : "+f"(acc[mt][nt][0]), "+f"(acc[mt][nt][1]),
                          "+f"(acc[mt][nt][2]), "+f"(acc[mt][nt][3])
                        : "r"(aF[mt][0]), "r"(aF[mt][1]), "r"(aF[mt][2]), "r"(aF[mt][3]),
                          "r"(bF[nt][0]), "r"(bF[nt][1]));
                }
        }
        __syncthreads();
    }

    // ---- epilogue ----
    #pragma unroll
    for (int mt = 0; mt < 2; mt++) {
        int m = r0 + wm + mt * 16 + (lane >> 2);
        #pragma unroll
        for (int nt = 0; nt < 8; nt++) {
            int n = n0 + wn + nt * 8 + (lane & 3) * 2;
            if (n < Nout) {
                float2 bb = *(const float2*)(bias + n);
                #pragma unroll
                for (int half_ : {0, 1}) {
                    int mr = m + half_ * 8;
                    if (mr < Mrows) {
                        float ox = acc[mt][nt][2 * half_] + bb.x;
                        float oy = acc[mt][nt][2 * half_ + 1] + bb.y;
                        if (sizeof(OutT) == 2) {
                            __half2 h = __floats2half2_rn(ox, oy);
                            *(__half2*)((__half*)C + (size_t)mr * Nout + n) = h;
                        } else {
                            float2 o = make_float2(ox, oy);
                            *(float2*)((float*)C + (size_t)mr * Nout + n) = o;
                        }
                    }
                }
            }
        }
    }
}

// ---------------- per-node attention logits ----------------
template <int C>
__global__ __launch_bounds__(256) void k_alpha(const float* __restrict__ att) {
    const int HC = 4 * C;
    const int PL = HC / 32;
    int gw = (blockIdx.x * blockDim.x + threadIdx.x) >> 5;
    int lane = threadIdx.x & 31;
    if (gw >= NN) return;
    const __half* row = d_Mh + (size_t)gw * HC + lane * PL;
    float s = 0.f;
    #pragma unroll
    for (int q = 0; q < PL / 2; q++) {
        __half2 hv = ((const __half2*)row)[q];
        float2 f = __half22float2(hv);
        s += f.x * att[lane * PL + 2 * q] + f.y * att[lane * PL + 2 * q + 1];
    }
    s += __shfl_xor_sync(0xffffffffu, s, 1);
    s += __shfl_xor_sync(0xffffffffu, s, 2);
    s += __shfl_xor_sync(0xffffffffu, s, 4);
    float a = (s > 0.f) ? s : 0.2f * s;
    if ((lane & 7) == 0) d_aN[(size_t)gw * 4 + (lane >> 3)] = a;
}

// ---------------- aggregation: one warp per destination node ----------------
template <int C>
__global__ __launch_bounds__(256) void k_agg(
    const float* __restrict__ resid, float* __restrict__ out)
{
    const int HC = 4 * C;
    const int PL = HC / 32;
    __shared__ float wsh[8][8][4];
    __shared__ int ssh[8][8];
    int gw = (blockIdx.x * blockDim.x + threadIdx.x) >> 5;
    int lane = threadIdx.x & 31;
    int wId = threadIdx.x >> 5;
    if (gw >= NN) return;
    int start = d_rowptr[gw], end = d_rowptr[gw + 1];

    float m0 = -INFINITY, m1 = -INFINITY, m2 = -INFINITY, m3 = -INFINITY;
    for (int i = start + lane; i < end; i += 32) {
        int s = d_csrsrc[i];
        float4 a = *(const float4*)(d_aN + (size_t)s * 4);
        m0 = fmaxf(m0, a.x);
        m1 = fmaxf(m1, a.y);
        m2 = fmaxf(m2, a.z);
        m3 = fmaxf(m3, a.w);
    }
    #pragma unroll
    for (int off = 16; off > 0; off >>= 1) {
        m0 = fmaxf(m0, __shfl_xor_sync(0xffffffffu, m0, off));
        m1 = fmaxf(m1, __shfl_xor_sync(0xffffffffu, m1, off));
        m2 = fmaxf(m2, __shfl_xor_sync(0xffffffffu, m2, off));
        m3 = fmaxf(m3, __shfl_xor_sync(0xffffffffu, m3, off));
    }
    int h = lane >> 3;
    int hh = lane & 3;
    float mhh = (hh == 0) ? m0 : (hh == 1) ? m1 : (hh == 2) ? m2 : m3;

    float acc[PL];
    #pragma unroll
    for (int j = 0; j < PL; j++) acc[j] = 0.f;
    float denL = 0.f;
    int ei = lane >> 2;

    for (int base = start; base < end; base += 8) {
        int ne = end - base;
        if (ne > 8) ne = 8;
        float wl = 0.f;
        int sl = 0;
        if (ei < ne) {
            sl = d_csrsrc[base + ei];
            float a = d_aN[(size_t)sl * 4 + hh];
            wl = expf(a - mhh);
            wsh[wId][ei][hh] = wl;
            if (hh == 0) ssh[wId][ei] = sl;
        }
        denL += wl;
        __syncwarp();
        for (int e = 0; e < ne; e++) {
            int s = ssh[wId][e];
            float w = wsh[wId][e][h];
            const __half* mrow = d_Mh + (size_t)s * HC + lane * PL;
            #pragma unroll
            for (int q = 0; q < PL / 2; q++) {
                __half2 hv = ((const __half2*)mrow)[q];
                float2 f = __half22float2(hv);
                acc[2 * q] += w * f.x;
                acc[2 * q + 1] += w * f.y;
            }
        }
        __syncwarp();
    }
    denL += __shfl_xor_sync(0xffffffffu, denL, 4);
    denL += __shfl_xor_sync(0xffffffffu, denL, 8);
    denL += __shfl_xor_sync(0xffffffffu, denL, 16);
    float den = __shfl_sync(0xffffffffu, denL, h);
    float inv = 0.25f / (den + 1e-16f);
    #pragma unroll
    for (int j = 0; j < PL; j++) {
        float v = acc[j] * inv;
        v += __shfl_xor_sync(0xffffffffu, v, 8);
        v += __shfl_xor_sync(0xffffffffu, v, 16);
        acc[j] = v;
    }
    if (lane < 8) {
        int col = lane * PL;
        #pragma unroll
        for (int q = 0; q < PL / 4; q++) {
            float4 r = *(const float4*)(resid + (size_t)gw * C + col + q * 4);
            float4 o;
            o.x = acc[q * 4 + 0] + r.x;
            o.y = acc[q * 4 + 1] + r.y;
            o.z = acc[q * 4 + 2] + r.z;
            o.w = acc[q * 4 + 3] + r.w;
            *(float4*)(out + (size_t)gw * C + col + q * 4) = o;
        }
    }
}

// ---------------- graph boundaries ----------------
__global__ void k_gstart(const int* __restrict__ batch) {
    int i = blockIdx.x * blockDim.x + threadIdx.x;
    if (i >= NN) return;
    int b = batch[i];
    int bp = (i == 0) ? -1 : batch[i - 1];
    for (int g = bp + 1; g <= b; g++) d_gstart[g] = i;
    if (i == NN - 1)
        for (int g = b + 1; g <= NG; g++) d_gstart[g] = NN;
}

// ---------------- global mean pool ----------------
__global__ void k_pool() {
    int g = blockIdx.x;
    int start = d_gstart[g], end = d_gstart[g + 1];
    int c = threadIdx.x & 63;
    int stripe = threadIdx.x >> 6;
    float acc = 0.f;
    for (int r = start + stripe; r < end; r += 4) acc += d_h3[(size_t)r * 64 + c];
    __shared__ float sh[256];
    sh[threadIdx.x] = acc;
    __syncthreads();
    if (stripe == 0) {
        float v = sh[c] + sh[c + 64] + sh[c + 128] + sh[c + 192];
        float cnt = (float)(end - start);
        d_pooled[g * 64 + c] = v / fmaxf(cnt, 1.0f);
    }
}

// ---------------- classifier + log_softmax ----------------
__global__ void k_fc(const float* __restrict__ Wfc, const float* __restrict__ bfc,
                     float* __restrict__ out) {
    int g = threadIdx.x;
    if (g >= NG) return;
    float logits[10];
    #pragma unroll
    for (int o = 0; o < 10; o++) {
        float s = bfc[o];
        for (int c = 0; c < 64; c++) s += d_pooled[g * 64 + c] * Wfc[c * 10 + o];
        logits[o] = s;
    }
    float mx = logits[0];
    #pragma unroll
    for (int o = 1; o < 10; o++) mx = fmaxf(mx, logits[o]);
    float se = 0.f;
    #pragma unroll
    for (int o = 0; o < 10; o++) se += expf(logits[o] - mx);
    float lse = mx + logf(se);
    #pragma unroll
    for (int o = 0; o < 10; o++) out[g * 10 + o] = logits[o] - lse;
}

// ---------------- launch ----------------
extern "C" void kernel_launch(void* const* d_in, const int* in_sizes, int n_in,
                              void* d_out, int out_size) {
    const float* x    = (const float*)d_in[0];
    const int* edge   = (const int*)d_in[1];
    const int* batch  = (const int*)d_in[2];
    const float* Wm1  = (const float*)d_in[3];
    const float* bm1  = (const float*)d_in[4];
    const float* att1 = (const float*)d_in[5];
    const float* Ws1  = (const float*)d_in[6];
    const float* bs1  = (const float*)d_in[7];
    const float* Wm2  = (const float*)d_in[8];
    const float* bm2  = (const float*)d_in[9];
    const float* att2 = (const float*)d_in[10];
    const float* Wm3  = (const float*)d_in[11];
    const float* bm3  = (const float*)d_in[12];
    const float* att3 = (const float*)d_in[13];
    const float* Ws3  = (const float*)d_in[14];
    const float* bs3  = (const float*)d_in[15];
    const float* Wfc  = (const float*)d_in[16];
    const float* bfc  = (const float*)d_in[17];
    float* out = (float*)d_out;

    const int* srcp = edge;
    const int* dstp = edge + NE;

    float *S, *h1, *h2, *h3;
    __half* Mh;
    cudaGetSymbolAddress((void**)&S, d_S);
    cudaGetSymbolAddress((void**)&h1, d_h1);
    cudaGetSymbolAddress((void**)&h2, d_h2);
    cudaGetSymbolAddress((void**)&h3, d_h3);
    cudaGetSymbolAddress((void**)&Mh, d_Mh);

    const int TB = 256;
    const int nodeBlocks = (NN + TB - 1) / TB;
    const int edgeBlocks = (NE + TB - 1) / TB;
    const int warpNodeBlocks = (NN * 32 + TB - 1) / TB;
    const int rowBlocks = (NN + 127) / 128;   // 391

    // CSR build
    k_zero_deg<<<nodeBlocks, TB>>>();
    k_degree<<<edgeBlocks, TB>>>(dstp);
    k_scan<<<1, 1024>>>();
    k_cursor<<<nodeBlocks, TB>>>();
    k_scatter<<<edgeBlocks, TB>>>(srcp, dstp);
    k_sort<<<nodeBlocks, TB>>>();

    // ---- layer 1: K=64 ----
    k_convW<<<(64 * 384 + TB - 1) / TB, TB>>>(Wm1, 64, 384);
    k_hgemm<__half><<<dim3(rowBlocks, 3), TB>>>(x, 64, bm1, Mh, NN, 384);
    k_convW<<<(64 * 96 + TB - 1) / TB, TB>>>(Ws1, 64, 96);
    k_hgemm<float><<<dim3(rowBlocks, 1), TB>>>(x, 64, bs1, S, NN, 96);
    k_alpha<96><<<warpNodeBlocks, TB>>>(att1);
    k_agg<96><<<warpNodeBlocks, TB>>>(S, h1);

    // ---- layer 2: K=96 ----
    k_convW<<<(96 * 384 + TB - 1) / TB, TB>>>(Wm2, 96, 384);
    k_hgemm<__half><<<dim3(rowBlocks, 3), TB>>>(h1, 96, bm2, Mh, NN, 384);
    k_alpha<96><<<warpNodeBlocks, TB>>>(att2);
    k_agg<96><<<warpNodeBlocks, TB>>>(h1, h2);

    // ---- layer 3: K=96 ----
    k_convW<<<(96 * 256 + TB - 1) / TB, TB>>>(Wm3, 96, 256);
    k_hgemm<__half><<<dim3(rowBlocks, 2), TB>>>(h2, 96, bm3, Mh, NN, 256);
    k_convW<<<(96 * 64 + TB - 1) / TB, TB>>>(Ws3, 96, 64);
    k_hgemm<float><<<dim3(rowBlocks, 1), TB>>>(h2, 96, bs3, S, NN, 64);
    k_alpha<64><<<warpNodeBlocks, TB>>>(att3);
    k_agg<64><<<warpNodeBlocks, TB>>>(S, h3);

    // ---- pool + classifier ----
    k_gstart<<<nodeBlocks, TB>>>(batch);
    k_pool<<<NG, 256>>>();
    k_fc<<<1, 64>>>(Wfc, bfc, out);
}